// round 17
// baseline (speedup 1.0000x reference)
#include <cuda_runtime.h>
#include <cuda_fp16.h>
#include <cstdint>

using f16 = __half;

constexpr int HIDDEN = 1024;
constexpr int INTER  = 1408;
constexpr int NEXP   = 8;
constexpr int TOKENS = 8192;
constexpr int MAX_MTILES = TOKENS / 128 + NEXP;   // 72
constexpr int NT1 = INTER / 64;                    // 22 GEMM1 n-tiles
constexpr int NT2 = HIDDEN / 128;                  // 8 GEMM2 n-tiles
constexpr int CVT_ITEMS = 44;                      // w2 convert work items
constexpr int G1_ITEMS = MAX_MTILES * NT1;         // 1584
constexpr int G2_ITEMS = MAX_MTILES * NT2;         // 576
constexpr int TOTAL_ITEMS = CVT_ITEMS + G1_ITEMS + G2_ITEMS;  // 2204
constexpr int WORKERS = 296;                       // 2 CTAs/SM x 148 SMs
constexpr int PREP_CTAS = 2048;

// ---------------- scratch (device globals; no allocation allowed) ----------
__device__ __align__(256) f16 g_x[(size_t)TOKENS * HIDDEN];
__device__ __align__(256) f16 g_w1[(size_t)NEXP * HIDDEN * 2 * INTER];  // [E][K][N]
__device__ __align__(256) f16 g_w2[(size_t)NEXP * INTER * HIDDEN];      // [E][K][N]
__device__ __align__(256) f16 g_h[(size_t)TOKENS * INTER];
__device__ int g_cnt_m[MAX_MTILES];   // GEMM1 n-tiles completed per m-tile
__device__ int g_cnt_cvt;             // w2 convert items completed
__device__ int g_queue;               // persistent work queue head

// ---------------- helpers ---------------------------------------------------
__device__ __forceinline__ bool map_tile(const void* tpe_ptr, int tile,
                                         int& eidx, int& off, int& cnt, int& m0) {
    int cnts[NEXP];
    const int* p32 = (const int*)tpe_ptr;
    int s = 0;
#pragma unroll
    for (int i = 0; i < NEXP; i++) s += p32[i];
    if (s == TOKENS) {
#pragma unroll
        for (int i = 0; i < NEXP; i++) cnts[i] = p32[i];
    } else {
        const long long* p64 = (const long long*)tpe_ptr;
#pragma unroll
        for (int i = 0; i < NEXP; i++) cnts[i] = (int)p64[i];
    }
    int acc_t = 0, acc_o = 0;
    bool found = false;
#pragma unroll
    for (int e = 0; e < NEXP; e++) {
        int t = (cnts[e] + 127) >> 7;
        if (!found && tile >= acc_t && tile < acc_t + t) {
            eidx = e; off = acc_o; cnt = cnts[e]; m0 = (tile - acc_t) * 128;
            found = true;
        }
        acc_t += t; acc_o += cnts[e];
    }
    return found;
}

__device__ __forceinline__ uint32_t smem_u32(const void* p) {
    uint32_t a;
    asm("{ .reg .u64 t; cvta.to.shared.u64 t, %1; cvt.u32.u64 %0, t; }"
        : "=r"(a) : "l"(p));
    return a;
}

#define SW128(o) ((o) ^ (((o) >> 3) & 0x70))

__device__ __forceinline__ void cp16(uint32_t s, const void* g, int nbytes) {
    asm volatile("cp.async.cg.shared.global [%0], [%1], 16, %2;"
                 :: "r"(s), "l"(g), "r"(nbytes) : "memory");
}

__device__ __forceinline__ void ldmx4(uint32_t* r, uint32_t addr) {
    asm volatile("ldmatrix.sync.aligned.m8n8.x4.shared.b16 {%0,%1,%2,%3}, [%4];"
                 : "=r"(r[0]), "=r"(r[1]), "=r"(r[2]), "=r"(r[3]) : "r"(addr));
}

__device__ __forceinline__ void ldmx4t(uint32_t* r, uint32_t addr) {
    asm volatile("ldmatrix.sync.aligned.m8n8.x4.trans.shared.b16 {%0,%1,%2,%3}, [%4];"
                 : "=r"(r[0]), "=r"(r[1]), "=r"(r[2]), "=r"(r[3]) : "r"(addr));
}

__device__ __forceinline__ void mma16816(float* c, const uint32_t* a, const uint32_t* b) {
    asm volatile("mma.sync.aligned.m16n8k16.row.col.f32.f16.f16.f32 "
                 "{%0,%1,%2,%3}, {%4,%5,%6,%7}, {%8,%9}, {%0,%1,%2,%3};"
                 : "+f"(c[0]), "+f"(c[1]), "+f"(c[2]), "+f"(c[3])
                 : "r"(a[0]), "r"(a[1]), "r"(a[2]), "r"(a[3]),
                   "r"(b[0]), "r"(b[1]));
}

__device__ __forceinline__ void cvt4(const float* __restrict__ src,
                                     f16* __restrict__ dst, size_t i) {
    float4 v = ((const float4*)src)[i];
    __half2 a = __floats2half2_rn(v.x, v.y);
    __half2 b = __floats2half2_rn(v.z, v.w);
    ((uint2*)dst)[i] = make_uint2(*(uint32_t*)&a, *(uint32_t*)&b);
}

// ---------------- prep kernel: counters + x & w1 converts (grid-stride) -----
__global__ __launch_bounds__(256) void prep_kernel(
    const float* __restrict__ x, f16* __restrict__ xf,
    const float* __restrict__ w1, f16* __restrict__ w1f,
    int nx4, int n14)
{
    if (blockIdx.x == 0 && threadIdx.x < MAX_MTILES + 2) {
        if (threadIdx.x < MAX_MTILES) g_cnt_m[threadIdx.x] = 0;
        else if (threadIdx.x == MAX_MTILES) g_cnt_cvt = 0;
        else g_queue = 0;
    }
    const int stride = PREP_CTAS * 256;
    const int base = blockIdx.x * 256 + threadIdx.x;
    const int total = nx4 + n14;

    int i = base;
    for (; i + 3 * stride < total; i += 4 * stride) {
#pragma unroll
        for (int u = 0; u < 4; ++u) {
            int j = i + u * stride;
            if (j < nx4) cvt4(x, xf, j);
            else         cvt4(w1, w1f, j - nx4);
        }
    }
    for (; i < total; i += stride) {
        if (i < nx4) cvt4(x, xf, i);
        else         cvt4(w1, w1f, i - nx4);
    }
}

// ---------------- GEMM body (shared by both GEMM phases) ---------------------
constexpr int BM = 128, BK = 64;
constexpr int A_SZ = BM * BK * 2;                // 16384
constexpr int B_SZ = BK * 128 * 2;               // 16384
constexpr int STAGE_SZ = A_SZ + B_SZ;            // 32768
constexpr int NSTAGE = 3;
constexpr int SMEM_BYTES = NSTAGE * STAGE_SZ;    // 98304 -> 2 CTAs/SM

template <int K, bool FUSED>
__device__ __forceinline__ void gemm_body(
    const f16* __restrict__ A, const f16* __restrict__ B,
    float* __restrict__ Cout, f16* __restrict__ H,
    int eidx, int off, int cnt, int m0, int ntile, char* smem)
{
    const int n0 = ntile * (FUSED ? 64 : 128);
    constexpr int NFULL = FUSED ? 2 * INTER : HIDDEN;

    const uint32_t sbase = smem_u32(smem);
    const int tid = threadIdx.x, wid = tid >> 5, lane = tid & 31;

    const f16* Ag = A + (size_t)off * K;
    const f16* Bg = B + (size_t)eidx * ((size_t)K * NFULL);

    const int wm = (wid & 1) * 64;
    const int wn = (wid >> 1) * 32;
    const int g = lane >> 3, r8 = lane & 7;

    int a_base[4];
#pragma unroll
    for (int mi = 0; mi < 4; mi++)
        a_base[mi] = (wm + mi * 16 + r8 + (g & 1) * 8) * 128 + (g >> 1) * 16;

    const int b_k_byte = ((g & 1) * 8 + r8) * 256;
    const int b_chunk_half = (g >> 1);

    const int a_row0 = tid >> 3, a_ks = tid & 7;
    const int b_k0 = tid >> 4, b_c = tid & 15;

    float acc[4][4][4];
#pragma unroll
    for (int mi = 0; mi < 4; mi++)
#pragma unroll
        for (int ni = 0; ni < 4; ni++)
#pragma unroll
            for (int q = 0; q < 4; q++) acc[mi][ni][q] = 0.0f;

    constexpr int NCH = K / BK;

    auto load_stage = [&](int c) {
        const uint32_t st = sbase + (c % NSTAGE) * STAGE_SZ;
        const int k0 = c * BK;
#pragma unroll
        for (int i = 0; i < 4; ++i) {
            int row = a_row0 + i * 32;
            int gr = m0 + row;
            int nb = (gr < cnt) ? 16 : 0;
            int grc = (gr < cnt) ? gr : 0;
            cp16(st + SW128(row * 128 + a_ks * 16),
                 Ag + (size_t)grc * K + k0 + a_ks * 8, nb);
        }
#pragma unroll
        for (int i = 0; i < 4; ++i) {
            int k = b_k0 + i * 16;
            int wc = b_c ^ (k & 7);
            int gcol = FUSED ? ((b_c < 8) ? (n0 + b_c * 8)
                                          : (INTER + n0 + (b_c - 8) * 8))
                             : (n0 + b_c * 8);
            cp16(st + A_SZ + k * 256 + wc * 16,
                 Bg + (size_t)(k0 + k) * NFULL + gcol, 16);
        }
        asm volatile("cp.async.commit_group;" ::: "memory");
    };

    load_stage(0);
    if (NCH > 1) load_stage(1);

    for (int c = 0; c < NCH; ++c) {
        if (c + 1 < NCH)
            asm volatile("cp.async.wait_group 1;" ::: "memory");
        else
            asm volatile("cp.async.wait_group 0;" ::: "memory");
        __syncthreads();
        if (c + 2 < NCH) load_stage(c + 2);

        const uint32_t st = sbase + (c % NSTAGE) * STAGE_SZ;
        const uint32_t sA = st, sB = st + A_SZ;

#pragma unroll
        for (int kk = 0; kk < 4; ++kk) {
            uint32_t b[4][2];
#pragma unroll
            for (int j = 0; j < 2; ++j) {
                int chunk = (((wn >> 3) + j * 2 + b_chunk_half) ^ r8) & 15;
                uint32_t t[4];
                ldmx4t(t, sB + kk * 16 * 256 + b_k_byte + chunk * 16);
                b[j * 2][0] = t[0];     b[j * 2][1] = t[1];
                b[j * 2 + 1][0] = t[2]; b[j * 2 + 1][1] = t[3];
            }
#pragma unroll
            for (int mi = 0; mi < 4; mi++) {
                uint32_t a[4];
                ldmx4(a, sA + SW128(a_base[mi] + kk * 32));
#pragma unroll
                for (int ni = 0; ni < 4; ni++)
                    mma16816(acc[mi][ni], a, b[ni]);
            }
        }
    }
    __syncthreads();

    // epilogue: stage accum through SMEM
    float* shf = (float*)smem;
    const int crow = wm + (lane >> 2);
    const int ccol0 = wn + (lane & 3) * 2;
#pragma unroll
    for (int mi = 0; mi < 4; mi++)
#pragma unroll
        for (int ni = 0; ni < 4; ni++) {
            int rr = crow + mi * 16, cc = ccol0 + ni * 8;
            *(float2*)&shf[rr * 132 + cc]       = make_float2(acc[mi][ni][0], acc[mi][ni][1]);
            *(float2*)&shf[(rr + 8) * 132 + cc] = make_float2(acc[mi][ni][2], acc[mi][ni][3]);
        }
    __syncthreads();

    if (FUSED) {
        for (int idx = tid; idx < 128 * 32; idx += 256) {
            int rr = idx >> 5, j = (idx & 31) * 2;
            if (m0 + rr >= cnt) continue;
            float g0 = shf[rr * 132 + j],      g1 = shf[rr * 132 + j + 1];
            float u0 = shf[rr * 132 + 64 + j], u1 = shf[rr * 132 + 64 + j + 1];
            float h0 = u0 * g0 / (1.0f + __expf(-g0));
            float h1 = u1 * g1 / (1.0f + __expf(-g1));
            __half2 hp = __floats2half2_rn(h0, h1);
            *(uint32_t*)(H + (size_t)(off + m0 + rr) * INTER + n0 + j) =
                *(uint32_t*)&hp;
        }
    } else {
        for (int idx = tid; idx < 128 * 32; idx += 256) {
            int rr = idx >> 5, cu = idx & 31;
            if (m0 + rr >= cnt) continue;
            *(float4*)(Cout + (size_t)(off + m0 + rr) * HIDDEN + n0 + cu * 4) =
                *(float4*)&shf[rr * 132 + cu * 4];
        }
    }
}

// ---------------- persistent mega kernel: work-stealing queue ---------------
__global__ __launch_bounds__(256, 2) void moe_mega(
    const f16* __restrict__ xf, const f16* __restrict__ w1f,
    const f16* __restrict__ w2f, f16* __restrict__ hf,
    float* __restrict__ out, const void* __restrict__ tpe,
    const float* __restrict__ w2src, int n24)
{
    extern __shared__ char smem[];
    __shared__ int sh_item;
    const int tid = threadIdx.x;

    for (;;) {
        // All threads have finished reading smem (epilogue) before arriving
        // here; the broadcast sync below also orders the next tile's writes.
        if (tid == 0) sh_item = atomicAdd(&g_queue, 1);
        __syncthreads();
        int item = sh_item;
        if (item >= TOTAL_ITEMS) return;
        __syncthreads();   // everyone has read sh_item; safe to reuse next loop

        if (item < CVT_ITEMS) {
            // w2 f32->f16 convert stripe (items 0..43, popped first)
            const int stride = CVT_ITEMS * 256;
            for (int i = item * 256 + tid; i < n24; i += stride)
                cvt4(w2src, (f16*)w2f, i);
            __threadfence();
            __syncthreads();
            if (tid == 0) atomicAdd(&g_cnt_cvt, 1);
            continue;
        }

        if (item < CVT_ITEMS + G1_ITEMS) {
            // GEMM1 (x @ w1 -> swiglu -> h), m-major item order
            int w = item - CVT_ITEMS;
            int mtile = w / NT1, ntile = w % NT1;
            int eidx, off, cnt, m0;
            if (!map_tile(tpe, mtile, eidx, off, cnt, m0)) continue;
            gemm_body<HIDDEN, true>(xf, w1f, nullptr, hf,
                                    eidx, off, cnt, m0, ntile, smem);
            __threadfence();
            __syncthreads();
            if (tid == 0) atomicAdd(&g_cnt_m[mtile], 1);
            continue;
        }

        // GEMM2 (h @ w2 -> out): wait for this m-tile's h and for w2f
        {
            int w = item - CVT_ITEMS - G1_ITEMS;
            int mtile = w / NT2, ntile = w % NT2;
            int eidx, off, cnt, m0;
            if (!map_tile(tpe, mtile, eidx, off, cnt, m0)) continue;
            if (tid == 0) {
                while (*(volatile int*)&g_cnt_cvt < CVT_ITEMS) __nanosleep(256);
                while (*(volatile int*)&g_cnt_m[mtile] < NT1) __nanosleep(256);
            }
            __syncthreads();
            __threadfence();
            gemm_body<INTER, false>(hf, w2f, out, nullptr,
                                    eidx, off, cnt, m0, ntile, smem);
        }
    }
}

// ---------------- launch -----------------------------------------------------
extern "C" void kernel_launch(void* const* d_in, const int* in_sizes, int n_in,
                              void* d_out, int out_size) {
    const float* x    = (const float*)d_in[0];
    const float* w1   = (const float*)d_in[1];
    const float* w2   = (const float*)d_in[2];
    const void*  tpe  = d_in[3];
    float* out = (float*)d_out;

    f16 *xf, *w1f, *w2f, *hf;
    cudaGetSymbolAddress((void**)&xf,  g_x);
    cudaGetSymbolAddress((void**)&w1f, g_w1);
    cudaGetSymbolAddress((void**)&w2f, g_w2);
    cudaGetSymbolAddress((void**)&hf,  g_h);

    int nx4 = TOKENS * HIDDEN / 4;
    int n14 = NEXP * HIDDEN * 2 * INTER / 4;
    int n24 = NEXP * INTER * HIDDEN / 4;

    // Launch 1: zero counters/queue + convert x and w1
    prep_kernel<<<PREP_CTAS, 256>>>(x, xf, w1, w1f, nx4, n14);

    // Launch 2: persistent mega kernel (296 workers, atomic work queue)
    cudaFuncSetAttribute(moe_mega,
                         cudaFuncAttributeMaxDynamicSharedMemorySize, SMEM_BYTES);
    moe_mega<<<WORKERS, 256, SMEM_BYTES>>>(xf, w1f, w2f, hf, out, tpe, w2, n24);
}